// round 6
// baseline (speedup 1.0000x reference)
#include <cuda_runtime.h>
#include <math.h>

#define NP2 64
#define NV  32768
#define WPB 8            // warps per block
#define VPW 2            // voxels per warp (16 lanes per voxel)
#define VPB (WPB * VPW)  // 16 voxels per block
// 16 lanes per voxel, 2 k-states per lane: lane ll holds k = (2ll, 2ll+1)

typedef unsigned long long u64;

// Per-pulse coefficients, pre-broadcast as {x,x} f32 pairs.
// [p][0]={ca2,sa2} [p][1]={ca,sa} [p][2]={hsa,cd} [p][3]={sd,-sd}
__device__ ulonglong2 g_cf[NP2][4];

__device__ __forceinline__ u64 dup_(float x) {
    u64 r; asm("mov.b64 %0,{%1,%1};" : "=l"(r) : "f"(x)); return r;
}

__global__ void precompute_coef_kernel(const float* __restrict__ thr,
                                       const float* __restrict__ thi) {
    int p = threadIdx.x;
    if (p >= NP2) return;
    float tr = thr[p], ti = thi[p];
    float a  = sqrtf(tr * tr + ti * ti);       // |theta| in (0.1, pi/2): never 0
    float inv_a = 1.0f / a;
    float cphi = tr * inv_a, sphi = ti * inv_a;
    float ca, sa;
    sincosf(a, &sa, &ca);
    float ca2 = 0.5f * (1.0f + ca);            // cos^2(a/2)
    float sa2 = 0.5f * (1.0f - ca);            // sin^2(a/2)
    float hsa = 0.5f * sa;

    // next pulse phase (delta twist); last pulse: delta = 0
    int pn = (p + 1 < NP2) ? p + 1 : p;
    float trn = thr[pn], tin = thi[pn];
    float an = sqrtf(trn * trn + tin * tin);
    float inv_an = 1.0f / an;
    float cphin = trn * inv_an, sphin = tin * inv_an;
    float cd = cphi * cphin + sphi * sphin;    // cos(phi_p - phi_{p+1})
    float sd = sphi * cphin - cphi * sphin;    // sin(phi_p - phi_{p+1})
    if (p + 1 >= NP2) { cd = 1.0f; sd = 0.0f; }

    g_cf[p][0] = make_ulonglong2(dup_(ca2), dup_(sa2));
    g_cf[p][1] = make_ulonglong2(dup_(ca),  dup_(sa));
    g_cf[p][2] = make_ulonglong2(dup_(hsa), dup_(cd));
    g_cf[p][3] = make_ulonglong2(dup_(sd),  dup_(-sd));
}

// ---- packed f32x2 helpers ----
__device__ __forceinline__ u64 bc(float x) {
    u64 r; asm("mov.b64 %0,{%1,%1};" : "=l"(r) : "f"(x)); return r;
}
__device__ __forceinline__ u64 pk(float a, float b) {
    u64 r; asm("mov.b64 %0,{%1,%2};" : "=l"(r) : "f"(a), "f"(b)); return r;
}
__device__ __forceinline__ void up(u64 v, float& a, float& b) {
    asm("mov.b64 {%0,%1},%2;" : "=f"(a), "=f"(b) : "l"(v));
}
__device__ __forceinline__ u64 f2(u64 a, u64 b, u64 c) {
    u64 d; asm("fma.rn.f32x2 %0,%1,%2,%3;" : "=l"(d) : "l"(a), "l"(b), "l"(c)); return d;
}
__device__ __forceinline__ u64 m2(u64 a, u64 b) {
    u64 d; asm("mul.rn.f32x2 %0,%1,%2;" : "=l"(d) : "l"(a), "l"(b)); return d;
}
__device__ __forceinline__ u64 s2(u64 a, u64 b) {
    u64 d; asm("sub.rn.f32x2 %0,%1,%2;" : "=l"(d) : "l"(a), "l"(b)); return d;
}
__device__ __forceinline__ u64 a2(u64 a, u64 b) {
    u64 d; asm("add.rn.f32x2 %0,%1,%2;" : "=l"(d) : "l"(a), "l"(b)); return d;
}

// 2 voxels per warp, 16 lanes per voxel, 2 k-states per lane (one pair).
__global__ __launch_bounds__(WPB * 32, 5)
void epg_kernel(const float* __restrict__ qmaps,   // [3, V]: PD, T1, T2
                const float* __restrict__ TRp,
                float* __restrict__ out) {          // [V, NP2]
    __shared__ ulonglong2 scf[NP2][4];              // 4KB coefficient table
    __shared__ float2 f0s[WPB][VPW][NP2 + 1];

    const int tid   = threadIdx.x;
    const int lane  = tid & 31;
    const int wid   = tid >> 5;
    const int sub   = lane >> 4;                    // voxel within warp (0/1)
    const int ll    = lane & 15;                    // lane within voxel
    const int vbase = blockIdx.x * VPB + wid * VPW;
    const int v     = vbase + sub;

    // cooperative copy of the coefficient table (256 threads, 256 entries)
    (&scf[0][0])[tid] = (&g_cf[0][0])[tid];

    const float TR = TRp[0];
    const float E1 = __expf(-TR / qmaps[NV + v]);
    const float E2 = __expf(-TR / qmaps[2 * NV + v]);
    const u64 E1p = bc(E1), E2p = bc(E2);
    const bool l0 = (ll == 0), l15 = (ll == 15);
    const u64 RecA = pk(l0 ? (1.0f - E1) : 0.0f, 0.0f);

    // Twisted-frame state: F+ (P), N=conj(F-), Z; one packed pair each.
    u64 Pr = 0, Pi = 0, Nr = 0, Ni = 0;
    u64 Zr = pk(l0 ? 1.0f : 0.0f, 0.0f), Zi = 0;

    __syncthreads();

    #pragma unroll 8
    for (int p = 0; p < NP2; p++) {
        const ulonglong2 q0 = scf[p][0];
        const ulonglong2 q1 = scf[p][1];
        const ulonglong2 q2 = scf[p][2];
        const ulonglong2 q3 = scf[p][3];
        const u64 Cca2 = q0.x, Csa2 = q0.y;
        const u64 Cca  = q1.x, Csa  = q1.y;
        const u64 Chsa = q2.x;
        // twist*relax multiplier u = E2 * e^{i(phi_p - phi_{p+1})}
        const u64 Ur  = m2(E2p, q2.y);
        const u64 Ui  = m2(E2p, q3.x);
        const u64 Nui = m2(E2p, q3.y);

        // Phase-factored matvec with N = conj(F-) (all-real coefficients)
        const u64 qzi = m2(Csa, Zi);
        const u64 qzr = m2(Csa, Zr);
        const u64 tPr = f2(Cca2, Pr, f2(Csa2, Nr, qzi));
        const u64 tPi = s2(m2(Cca2, Pi), f2(Csa2, Ni, qzr));
        const u64 tNr = s2(f2(Csa2, Pr, m2(Cca2, Nr)), qzi);
        const u64 tNi = s2(m2(Cca2, Ni), f2(Csa2, Pi, qzr));
        const u64 tZr = f2(Cca, Zr, m2(Chsa, a2(Pi, Ni)));
        const u64 tZi = f2(Cca, Zi, m2(Chsa, s2(Nr, Pr)));

        float PrL, PrH, PiL, PiH, NrL, NrH, NiL, NiH;
        up(tPr, PrL, PrH); up(tPi, PiL, PiH);
        up(tNr, NrL, NrH); up(tNi, NiL, NiH);

        // F0 = tP at k=0 pre-shift
        if (l0) f0s[wid][sub][p] = make_float2(PrL, PiL);

        // EPG shift: P up in k, N down in k (within 16-lane voxel group).
        // Boundary P_0 <- N_1 is INTRA-thread (own NrH/NiH); N_31 <- 0.
        float inPr = __shfl_up_sync(0xffffffffu, PrH, 1, 16);
        float inPi = __shfl_up_sync(0xffffffffu, PiH, 1, 16);
        float inNr = __shfl_down_sync(0xffffffffu, NrL, 1, 16);
        float inNi = __shfl_down_sync(0xffffffffu, NiL, 1, 16);
        if (l0)  { inPr = NrH; inPi = NiH; }
        if (l15) { inNr = 0.0f; inNi = 0.0f; }

        const u64 Xr = pk(inPr, PrL), Xi = pk(inPi, PiL);
        const u64 Yr = pk(NrH, inNr), Yi = pk(NiH, inNi);

        // twist+relax: both P and N multiply by u; Z: E1 (+recovery at k=0)
        Pr = f2(Ur, Xr, m2(Nui, Xi));  Pi = f2(Ur, Xi, m2(Ui, Xr));
        Nr = f2(Ur, Yr, m2(Nui, Yi));  Ni = f2(Ur, Yi, m2(Ui, Yr));
        Zr = f2(E1p, tZr, RecA);       Zi = m2(E1p, tZi);
    }

    __syncwarp();

    // Epilogue: |F0| * PD; 2 consecutive voxels per warp -> coalesced stores
    const float* pdp = qmaps + vbase;
    float* ob = out + (size_t)vbase * NP2;
    #pragma unroll
    for (int i = 0; i < (VPW * NP2) / 32; i++) {
        int flat = i * 32 + lane;
        int vv   = flat >> 6;
        int idx  = flat & 63;
        float2 f = f0s[wid][vv][idx];
        ob[flat] = sqrtf(f.x * f.x + f.y * f.y) * pdp[vv];
    }
}

extern "C" void kernel_launch(void* const* d_in, const int* in_sizes, int n_in,
                              void* d_out, int out_size) {
    const float* theta_re = (const float*)d_in[0];   // [64]
    const float* theta_im = (const float*)d_in[1];   // [64]
    const float* TR       = (const float*)d_in[2];   // [1]
    const float* qmaps    = (const float*)d_in[3];   // [3, 32768, 1]
    float* out = (float*)d_out;                      // [32768, 64]

    precompute_coef_kernel<<<1, 64>>>(theta_re, theta_im);
    epg_kernel<<<NV / VPB, WPB * 32>>>(qmaps, TR, out);
}

// round 7
// speedup vs baseline: 1.1061x; 1.1061x over previous
#include <cuda_runtime.h>
#include <math.h>

#define NP2 64
#define NV  32768
#define WPB 4            // warps per block
#define VPW 4            // voxels per warp
// 8 lanes per voxel, 4 k-states per lane (two f32x2 pairs per component)

typedef unsigned long long u64;

// Per-pulse coefficients, pre-broadcast as {x,x} f32 pairs.
// [p][0]={ca,sa} [p][1]={-sa,cd} [p][2]={sd,-sd}
__device__ ulonglong2 g_cf[NP2][3];

__device__ __forceinline__ u64 dup_(float x) {
    u64 r; asm("mov.b64 %0,{%1,%1};" : "=l"(r) : "f"(x)); return r;
}

__global__ void precompute_coef_kernel(const float* __restrict__ thr,
                                       const float* __restrict__ thi) {
    int p = threadIdx.x;
    if (p >= NP2) return;
    float tr = thr[p], ti = thi[p];
    float a  = sqrtf(tr * tr + ti * ti);       // |theta| in (0.1, pi/2): never 0
    float inv_a = 1.0f / a;
    float cphi = tr * inv_a, sphi = ti * inv_a;
    float ca, sa;
    sincosf(a, &sa, &ca);

    // next pulse phase (delta twist); last pulse: delta = 0
    int pn = (p + 1 < NP2) ? p + 1 : p;
    float trn = thr[pn], tin = thi[pn];
    float an = sqrtf(trn * trn + tin * tin);
    float inv_an = 1.0f / an;
    float cphin = trn * inv_an, sphin = tin * inv_an;
    float cd = cphi * cphin + sphi * sphin;    // cos(phi_p - phi_{p+1})
    float sd = sphi * cphin - cphi * sphin;    // sin(phi_p - phi_{p+1})
    if (p + 1 >= NP2) { cd = 1.0f; sd = 0.0f; }

    g_cf[p][0] = make_ulonglong2(dup_(ca),  dup_(sa));
    g_cf[p][1] = make_ulonglong2(dup_(-sa), dup_(cd));
    g_cf[p][2] = make_ulonglong2(dup_(sd),  dup_(-sd));
}

// ---- packed f32x2 helpers ----
__device__ __forceinline__ u64 bc(float x) {
    u64 r; asm("mov.b64 %0,{%1,%1};" : "=l"(r) : "f"(x)); return r;
}
__device__ __forceinline__ u64 pk(float a, float b) {
    u64 r; asm("mov.b64 %0,{%1,%2};" : "=l"(r) : "f"(a), "f"(b)); return r;
}
__device__ __forceinline__ void up(u64 v, float& a, float& b) {
    asm("mov.b64 {%0,%1},%2;" : "=f"(a), "=f"(b) : "l"(v));
}
__device__ __forceinline__ u64 f2(u64 a, u64 b, u64 c) {
    u64 d; asm("fma.rn.f32x2 %0,%1,%2,%3;" : "=l"(d) : "l"(a), "l"(b), "l"(c)); return d;
}
__device__ __forceinline__ u64 m2(u64 a, u64 b) {
    u64 d; asm("mul.rn.f32x2 %0,%1,%2;" : "=l"(d) : "l"(a), "l"(b)); return d;
}
__device__ __forceinline__ u64 s2(u64 a, u64 b) {
    u64 d; asm("sub.rn.f32x2 %0,%1,%2;" : "=l"(d) : "l"(a), "l"(b)); return d;
}
__device__ __forceinline__ u64 a2(u64 a, u64 b) {
    u64 d; asm("add.rn.f32x2 %0,%1,%2;" : "=l"(d) : "l"(a), "l"(b)); return d;
}

// hS/hD-form EPG matvec (12 f32x2 per packed pair):
//   hS=(P+N)/2, hD=(P-N)/2; tP = hS+w, tN = hS-w (real), tP/tN imag via vi;
//   tZr = ca Zr + sa hSi, tZi = ca Zi - sa hDr.
#define MATVEC(S) \
  u64 w_##S   = f2(Cca, hDr_##S, m2(Csa, Zi_##S)); \
  u64 vi_##S  = f2(Cca, hSi_##S, m2(Cnsa, Zr_##S)); \
  u64 tPr_##S = a2(hSr_##S, w_##S); \
  u64 tNr_##S = s2(hSr_##S, w_##S); \
  u64 tPi_##S = a2(vi_##S, hDi_##S); \
  u64 tNi_##S = s2(vi_##S, hDi_##S); \
  u64 tZr_##S = f2(Cca, Zr_##S, m2(Csa, hSi_##S)); \
  u64 tZi_##S = f2(Cnsa, hDr_##S, m2(Cca, Zi_##S));

// 4 voxels per warp, 8 lanes per voxel, 4 k-states per lane:
// lane ll (0..7) holds k = 4*ll + {0,1,2,3}; pair a = (k0,k1), pair b = (k2,k3).
__global__ __launch_bounds__(WPB * 32, 9)
void epg_kernel(const float* __restrict__ qmaps,   // [3, V]: PD, T1, T2
                const float* __restrict__ TRp,
                float* __restrict__ out) {          // [V, NP2]
    __shared__ ulonglong2 scf[NP2][3];              // 3KB coefficient table
    __shared__ float2 f0s[WPB][VPW][NP2 + 1];

    const int tid   = threadIdx.x;
    const int lane  = tid & 31;
    const int wid   = tid >> 5;
    const int sub   = lane >> 3;                    // voxel within warp
    const int ll    = lane & 7;                     // lane within voxel
    const int vbase = blockIdx.x * (WPB * VPW) + wid * VPW;
    const int v     = vbase + sub;

    // cooperative copy of the coefficient table (192 entries, 128 threads)
    {
        const ulonglong2* src = &g_cf[0][0];
        ulonglong2* dst = &scf[0][0];
        for (int i = tid; i < NP2 * 3; i += WPB * 32) dst[i] = src[i];
    }

    const float TR = TRp[0];
    const float E1 = __expf(-TR / qmaps[NV + v]);
    const float E2 = __expf(-TR / qmaps[2 * NV + v]);
    const u64 E1p = bc(E1), E2h = bc(0.5f * E2);
    const bool l0 = (ll == 0), l7 = (ll == 7);
    const u64 RecA = pk(l0 ? (1.0f - E1) : 0.0f, 0.0f);

    // State: hS=(P+N)/2, hD=(P-N)/2, Z; complex, 2 packed pairs each.
    u64 hSr_a = 0, hSr_b = 0, hSi_a = 0, hSi_b = 0;
    u64 hDr_a = 0, hDr_b = 0, hDi_a = 0, hDi_b = 0;
    u64 Zr_a = pk(l0 ? 1.0f : 0.0f, 0.0f), Zr_b = 0, Zi_a = 0, Zi_b = 0;

    __syncthreads();

    #pragma unroll 4
    for (int p = 0; p < NP2; p++) {
        const ulonglong2 q0 = scf[p][0];
        const ulonglong2 q1 = scf[p][1];
        const ulonglong2 q2 = scf[p][2];
        const u64 Cca  = q0.x, Csa  = q0.y;
        const u64 Cnsa = q1.x;
        // uh = (E2/2) * e^{i(phi_p - phi_{p+1})}
        const u64 Uhr  = m2(E2h, q1.y);
        const u64 Uhi  = m2(E2h, q2.x);
        const u64 NUhi = m2(E2h, q2.y);

        MATVEC(a)
        MATVEC(b)

        // unpack the pieces the shift needs
        float aPrL, aPrH, bPrL, bPrH, aPiL, aPiH, bPiL, bPiH;
        up(tPr_a, aPrL, aPrH); up(tPr_b, bPrL, bPrH);
        up(tPi_a, aPiL, aPiH); up(tPi_b, bPiL, bPiH);
        float aNrL, aNrH, bNrL, bNrH, aNiL, aNiH, bNiL, bNiH;
        up(tNr_a, aNrL, aNrH); up(tNr_b, bNrL, bNrH);
        up(tNi_a, aNiL, aNiH); up(tNi_b, bNiL, bNiH);

        // F0 = tP at k=0 pre-shift; frame phase drops under |.|
        if (l0) f0s[wid][sub][p] = make_float2(aPrL, aPiL);

        // EPG shift: P up in k, N (=conj F-) down in k;
        // boundary: P_0 <- N_1 (no conj), N_31 <- 0.
        float inPr = __shfl_up_sync(0xffffffffu, bPrH, 1);
        float inPi = __shfl_up_sync(0xffffffffu, bPiH, 1);
        float inNr = __shfl_down_sync(0xffffffffu, aNrL, 1);
        float inNi = __shfl_down_sync(0xffffffffu, aNiL, 1);
        if (l0) { inPr = aNrH; inPi = aNiH; }
        if (l7) { inNr = 0.0f; inNi = 0.0f; }

        // repack shifted values: X = Shift(tP), Y = Shift(tN)
        const u64 Xr_a = pk(inPr, aPrL), Xr_b = pk(aPrH, bPrL);
        const u64 Xi_a = pk(inPi, aPiL), Xi_b = pk(aPiH, bPiL);
        const u64 Yr_a = pk(aNrH, bNrL), Yr_b = pk(bNrH, inNr);
        const u64 Yi_a = pk(aNiH, bNiL), Yi_b = pk(bNiH, inNi);

        // sums/diffs, then twist-relax: hS' = uh*(X+Y), hD' = uh*(X-Y)
        const u64 Ar_a = a2(Xr_a, Yr_a), Ar_b = a2(Xr_b, Yr_b);
        const u64 Ai_a = a2(Xi_a, Yi_a), Ai_b = a2(Xi_b, Yi_b);
        const u64 Br_a = s2(Xr_a, Yr_a), Br_b = s2(Xr_b, Yr_b);
        const u64 Bi_a = s2(Xi_a, Yi_a), Bi_b = s2(Xi_b, Yi_b);

        hSr_a = f2(Uhr, Ar_a, m2(NUhi, Ai_a));  hSr_b = f2(Uhr, Ar_b, m2(NUhi, Ai_b));
        hSi_a = f2(Uhr, Ai_a, m2(Uhi , Ar_a));  hSi_b = f2(Uhr, Ai_b, m2(Uhi , Ar_b));
        hDr_a = f2(Uhr, Br_a, m2(NUhi, Bi_a));  hDr_b = f2(Uhr, Br_b, m2(NUhi, Bi_b));
        hDi_a = f2(Uhr, Bi_a, m2(Uhi , Br_a));  hDi_b = f2(Uhr, Bi_b, m2(Uhi , Br_b));
        Zr_a  = f2(E1p, tZr_a, RecA);           Zr_b  = m2(E1p, tZr_b);
        Zi_a  = m2(E1p, tZi_a);                 Zi_b  = m2(E1p, tZi_b);
    }

    __syncwarp();

    // Epilogue: |F0| * PD; 4 consecutive voxels per warp -> coalesced stores
    const float* pdp = qmaps + vbase;
    float* ob = out + (size_t)vbase * NP2;
    #pragma unroll
    for (int i = 0; i < (VPW * NP2) / 32; i++) {
        int flat = i * 32 + lane;
        int vv   = flat >> 6;
        int idx  = flat & 63;
        float2 f = f0s[wid][vv][idx];
        ob[flat] = sqrtf(f.x * f.x + f.y * f.y) * pdp[vv];
    }
}

extern "C" void kernel_launch(void* const* d_in, const int* in_sizes, int n_in,
                              void* d_out, int out_size) {
    const float* theta_re = (const float*)d_in[0];   // [64]
    const float* theta_im = (const float*)d_in[1];   // [64]
    const float* TR       = (const float*)d_in[2];   // [1]
    const float* qmaps    = (const float*)d_in[3];   // [3, 32768, 1]
    float* out = (float*)d_out;                      // [32768, 64]

    precompute_coef_kernel<<<1, 64>>>(theta_re, theta_im);
    epg_kernel<<<NV / (WPB * VPW), WPB * 32>>>(qmaps, TR, out);
}